// round 7
// baseline (speedup 1.0000x reference)
#include <cuda_runtime.h>
#include <cuda_bf16.h>
#include <math.h>

#define NN 100000
#define EE 1600000
#define FIN 128
#define HID 32
#define HEADS 8
#define D1 256        // HEADS*HID
#define NCLS 40
#define BETA 0.1f
#define ONE_MB 0.9f   // 1-beta
#define LRA 0.2f      // leaky relu alpha
#define SCB 1024
#define NBLK ((NN + SCB - 1) / SCB)

// ------------- scratch (device globals; total ~237 MB, < 256 MB) -------------
__device__ __align__(128) float g_H0[(size_t)NN * D1];    // x@Wcat; layer-1 out in place
__device__ __align__(128) float g_FA[(size_t)NN * 128];   // hop-1 scratch; reused as GA
__device__ __align__(128) float g_O0[(size_t)NN * NCLS];  // H @ W_out
__device__ __align__(128) float g_WBUF[2][(size_t)EE * 4];// unnorm attn w, group-packed
__device__ __align__(128) int   g_SSRC[EE];               // src sorted by dst (CSR)
__device__ __align__(128) float g_S8[(size_t)NN * 8];
__device__ __align__(128) float g_T8[(size_t)NN * 8];
__device__ __align__(128) float g_INV8[(size_t)NN * 8];
__device__ int   g_ROWPTR[NN + 1];
__device__ int   g_DEG[NN];
__device__ int   g_CUR[NN];
__device__ int   g_BSUM[NBLK];
__device__ int   g_BOFF[NBLK];
__device__ int   g_EI64;

// ------------------------------- helpers --------------------------------------
__device__ __forceinline__ float warp_sum(float v) {
#pragma unroll
    for (int o = 16; o > 0; o >>= 1) v += __shfl_xor_sync(0xffffffffu, v, o);
    return v;
}
__device__ __forceinline__ float warp_max(float v) {
#pragma unroll
    for (int o = 16; o > 0; o >>= 1) v = fmaxf(v, __shfl_xor_sync(0xffffffffu, v, o));
    return v;
}
__device__ __forceinline__ int warp_sum_i(int v) {
#pragma unroll
    for (int o = 16; o > 0; o >>= 1) v += __shfl_xor_sync(0xffffffffu, v, o);
    return v;
}
__device__ __forceinline__ float sel4(float4 w, int h) {
    return (h == 0) ? w.x : (h == 1) ? w.y : (h == 2) ? w.z : w.w;
}

// ------------------------- edge dtype sniff (parallel) -------------------------
__global__ void sniff_kernel(const int* __restrict__ ei32) {
    int bad = 0;
    for (int i = threadIdx.x; i < 512; i += 256)
        bad |= (ei32[2 * i + 1] != 0);
    bad = __syncthreads_or(bad);
    if (threadIdx.x == 0) g_EI64 = bad ? 0 : 1;
}

__device__ __forceinline__ int load_node(const void* ei, size_t pos, int is64) {
    if (is64) return (int)((const long long*)ei)[pos];
    return ((const int*)ei)[pos];
}

// ------------------------------ CSR build -------------------------------------
__global__ void zero_counts_kernel() {
    int i = blockIdx.x * blockDim.x + threadIdx.x;
    if (i < NN) { g_DEG[i] = 0; g_CUR[i] = 0; }
}

__global__ void build_deg_kernel(const void* __restrict__ ei) {
    int e = blockIdx.x * blockDim.x + threadIdx.x;
    if (e >= EE) return;
    int d = load_node(ei, (size_t)EE + e, g_EI64);
    if ((unsigned)d < NN) atomicAdd(&g_DEG[d], 1);
}

__global__ void scanA_kernel() {
    __shared__ int wsum[8];
    int tid = threadIdx.x;
    int base = blockIdx.x * SCB + tid * 4;
    int s = 0;
#pragma unroll
    for (int j = 0; j < 4; j++) { int i = base + j; if (i < NN) s += g_DEG[i]; }
    s = warp_sum_i(s);
    if ((tid & 31) == 0) wsum[tid >> 5] = s;
    __syncthreads();
    if (tid == 0) {
        int t = 0;
#pragma unroll
        for (int w = 0; w < 8; w++) t += wsum[w];
        g_BSUM[blockIdx.x] = t;
    }
}

__global__ void scanB_kernel() {
    __shared__ int sm[4];
    int tid = threadIdx.x, lane = tid & 31, wid = tid >> 5;
    int v = (tid < NBLK) ? g_BSUM[tid] : 0;
    int x = v;
#pragma unroll
    for (int o = 1; o < 32; o <<= 1) {
        int y = __shfl_up_sync(0xffffffffu, x, o);
        if (lane >= o) x += y;
    }
    if (lane == 31) sm[wid] = x;
    __syncthreads();
    int woff = 0;
    for (int w = 0; w < wid; w++) woff += sm[w];
    if (tid < NBLK) g_BOFF[tid] = woff + x - v;
}

__global__ void scanC_kernel() {
    __shared__ int wsum[8];
    int tid = threadIdx.x, lane = tid & 31, wid = tid >> 5;
    int base = blockIdx.x * SCB + tid * 4;
    int a0 = (base + 0 < NN) ? g_DEG[base + 0] : 0;
    int a1 = (base + 1 < NN) ? g_DEG[base + 1] : 0;
    int a2 = (base + 2 < NN) ? g_DEG[base + 2] : 0;
    int a3 = (base + 3 < NN) ? g_DEG[base + 3] : 0;
    int tsum = a0 + a1 + a2 + a3;
    int x = tsum;
#pragma unroll
    for (int o = 1; o < 32; o <<= 1) {
        int y = __shfl_up_sync(0xffffffffu, x, o);
        if (lane >= o) x += y;
    }
    if (lane == 31) wsum[wid] = x;
    __syncthreads();
    int woff = 0;
    for (int w = 0; w < wid; w++) woff += wsum[w];
    int excl = g_BOFF[blockIdx.x] + woff + (x - tsum);
    if (base + 0 < NN) g_ROWPTR[base + 1] = excl + a0;
    if (base + 1 < NN) g_ROWPTR[base + 2] = excl + a0 + a1;
    if (base + 2 < NN) g_ROWPTR[base + 3] = excl + a0 + a1 + a2;
    if (base + 3 < NN) g_ROWPTR[base + 4] = excl + tsum;
    if (blockIdx.x == 0 && tid == 0) g_ROWPTR[0] = 0;
}

__global__ void scatter_kernel(const void* __restrict__ ei) {
    int e = blockIdx.x * blockDim.x + threadIdx.x;
    if (e >= EE) return;
    int is64 = g_EI64;
    int s = load_node(ei, (size_t)e, is64);
    int d = load_node(ei, (size_t)EE + e, is64);
    if ((unsigned)d >= NN || (unsigned)s >= NN) return;
    int pos = g_ROWPTR[d] + atomicAdd(&g_CUR[d], 1);
    if ((unsigned)pos < EE) g_SSRC[pos] = s;
}

// --------------------------------- GEMM1 --------------------------------------
__global__ void __launch_bounds__(256) gemm1_kernel(const float* __restrict__ x,
                                                    const float* __restrict__ W) {
    __shared__ float As[32][132];
    __shared__ float Bs[32][68];
    int tid = threadIdx.x;
    int tx = tid & 15;
    int ty = tid >> 4;
    int rowBase = blockIdx.x * 128;
    int colBase = blockIdx.y * 64;
    float acc[8][4] = {};
    for (int kt = 0; kt < FIN; kt += 32) {
#pragma unroll
        for (int p = 0; p < 4; p++) {
            int idx = tid + p * 256;
            int r = idx & 127;
            int kq = idx >> 7;
            int gr = rowBase + r;
            float4 v = make_float4(0.f, 0.f, 0.f, 0.f);
            if (gr < NN) v = *(const float4*)&x[(size_t)gr * FIN + kt + kq * 4];
            As[kq * 4 + 0][r] = v.x;
            As[kq * 4 + 1][r] = v.y;
            As[kq * 4 + 2][r] = v.z;
            As[kq * 4 + 3][r] = v.w;
        }
#pragma unroll
        for (int p = 0; p < 8; p++) {
            int idx = tid + p * 256;
            int nn = idx & 63;
            int k = idx >> 6;
            int col = colBase + nn;
            Bs[k][nn] = W[(size_t)(col >> 5) * (FIN * HID) + (size_t)(kt + k) * HID + (col & 31)];
        }
        __syncthreads();
#pragma unroll
        for (int k = 0; k < 32; k++) {
            float4 a0 = *(const float4*)&As[k][ty * 8];
            float4 a1 = *(const float4*)&As[k][ty * 8 + 4];
            float4 b  = *(const float4*)&Bs[k][tx * 4];
            float am[8] = {a0.x, a0.y, a0.z, a0.w, a1.x, a1.y, a1.z, a1.w};
            float bn[4] = {b.x, b.y, b.z, b.w};
#pragma unroll
            for (int i = 0; i < 8; i++)
#pragma unroll
                for (int j = 0; j < 4; j++)
                    acc[i][j] += am[i] * bn[j];
        }
        __syncthreads();
    }
#pragma unroll
    for (int i = 0; i < 8; i++) {
        int gr = rowBase + ty * 8 + i;
        if (gr < NN)
            *(float4*)&g_H0[(size_t)gr * D1 + colBase + tx * 4] =
                make_float4(acc[i][0], acc[i][1], acc[i][2], acc[i][3]);
    }
}

// --------------------------------- GEMM2 --------------------------------------
__global__ void gemm2_kernel(const float* __restrict__ Wout) {
    __shared__ float Bs[D1 * NCLS];
    int tid = threadIdx.x;
    for (int i = tid; i < D1 * NCLS; i += 256) Bs[i] = Wout[i];
    __syncthreads();
    int row = blockIdx.x * 256 + tid;
    if (row >= NN) return;
    const float* arow = g_H0 + (size_t)row * D1;
    float acc[NCLS] = {};
#pragma unroll 2
    for (int k4 = 0; k4 < D1; k4 += 4) {
        float4 a = *(const float4*)(arow + k4);
        float av[4] = {a.x, a.y, a.z, a.w};
#pragma unroll
        for (int kk = 0; kk < 4; kk++) {
            float av1 = av[kk];
            const float* b = &Bs[(k4 + kk) * NCLS];
#pragma unroll
            for (int c = 0; c < NCLS; c++) acc[c] += av1 * b[c];
        }
    }
    float* orow = g_O0 + (size_t)row * NCLS;
#pragma unroll
    for (int c = 0; c < NCLS; c++) orow[c] = acc[c];
}

// --------------------- attention s,t for ALL 8 heads at once ------------------
__global__ void st8_kernel(const float* __restrict__ a_src,
                           const float* __restrict__ a_dst) {
    int gw = blockIdx.x * 8 + (threadIdx.x >> 5);
    int lane = threadIdx.x & 31;
    if (gw >= NN) return;
    const float* row = g_H0 + (size_t)gw * D1;
#pragma unroll
    for (int h = 0; h < HEADS; h++) {
        float v = row[h * HID + lane];
        float s = warp_sum(v * a_src[h * HID + lane]);
        float t = warp_sum(v * a_dst[h * HID + lane]);
        if (lane == 0) { g_S8[(size_t)gw * 8 + h] = s; g_T8[(size_t)gw * 8 + h] = t; }
    }
}

// ------------ 8-head fused attention weights (unnormalized) + INV --------------
__global__ void attn8_kernel() {
    int d = blockIdx.x * 8 + (threadIdx.x >> 5);
    int lane = threadIdx.x & 31;
    if (d >= NN) return;
    int start = g_ROWPTR[d], end = g_ROWPTR[d + 1];
    if (start == end) {
        if (lane == 0) {
            float4 z = make_float4(0.f, 0.f, 0.f, 0.f);
            *(float4*)&g_INV8[(size_t)d * 8] = z;
            *(float4*)&g_INV8[(size_t)d * 8 + 4] = z;
        }
        return;
    }
    float4 ta = *(const float4*)&g_T8[(size_t)d * 8];
    float4 tb = *(const float4*)&g_T8[(size_t)d * 8 + 4];
    float t[8] = {ta.x, ta.y, ta.z, ta.w, tb.x, tb.y, tb.z, tb.w};
    float m[8];
#pragma unroll
    for (int i = 0; i < 8; i++) m[i] = -INFINITY;
    for (int e = start + lane; e < end; e += 32) {
        int s = g_SSRC[e];
        float4 sa = *(const float4*)&g_S8[(size_t)s * 8];
        float4 sb = *(const float4*)&g_S8[(size_t)s * 8 + 4];
        float sv[8] = {sa.x, sa.y, sa.z, sa.w, sb.x, sb.y, sb.z, sb.w};
#pragma unroll
        for (int i = 0; i < 8; i++) {
            float ev = sv[i] + t[i];
            ev = (ev >= 0.f) ? ev : LRA * ev;
            m[i] = fmaxf(m[i], ev);
        }
    }
#pragma unroll
    for (int i = 0; i < 8; i++) m[i] = warp_max(m[i]);
    float u[8] = {};
    for (int e = start + lane; e < end; e += 32) {
        int s = g_SSRC[e];
        float4 sa = *(const float4*)&g_S8[(size_t)s * 8];
        float4 sb = *(const float4*)&g_S8[(size_t)s * 8 + 4];
        float sv[8] = {sa.x, sa.y, sa.z, sa.w, sb.x, sb.y, sb.z, sb.w};
        float p[8];
#pragma unroll
        for (int i = 0; i < 8; i++) {
            float ev = sv[i] + t[i];
            ev = (ev >= 0.f) ? ev : LRA * ev;
            p[i] = expf(ev - m[i]);
            u[i] += p[i];
        }
        *(float4*)&g_WBUF[0][(size_t)e * 4] = make_float4(p[0], p[1], p[2], p[3]);
        *(float4*)&g_WBUF[1][(size_t)e * 4] = make_float4(p[4], p[5], p[6], p[7]);
    }
#pragma unroll
    for (int i = 0; i < 8; i++) u[i] = warp_sum(u[i]);
    if (lane == 0) {
        *(float4*)&g_INV8[(size_t)d * 8] =
            make_float4(1.f / (u[0] + 1e-16f), 1.f / (u[1] + 1e-16f),
                        1.f / (u[2] + 1e-16f), 1.f / (u[3] + 1e-16f));
        *(float4*)&g_INV8[(size_t)d * 8 + 4] =
            make_float4(1.f / (u[4] + 1e-16f), 1.f / (u[5] + 1e-16f),
                        1.f / (u[6] + 1e-16f), 1.f / (u[7] + 1e-16f));
    }
}

// ------------------ 4-head fused diffusion hop (warp per dst) -----------------
__global__ void hop4_kernel(int g, int mode) {
    int d = blockIdx.x * 8 + (threadIdx.x >> 5);
    int lane = threadIdx.x & 31;
    if (d >= NN) return;
    int h = lane >> 3;
    int start = g_ROWPTR[d], end = g_ROWPTR[d + 1];
    const float* wb = g_WBUF[g];
    float4 acc = make_float4(0.f, 0.f, 0.f, 0.f);
    int e = start;
    for (; e + 4 <= end; e += 4) {
        int s0 = g_SSRC[e], s1 = g_SSRC[e + 1], s2 = g_SSRC[e + 2], s3 = g_SSRC[e + 3];
        float4 w0 = *(const float4*)&wb[(size_t)e * 4];
        float4 w1 = *(const float4*)&wb[(size_t)(e + 1) * 4];
        float4 w2 = *(const float4*)&wb[(size_t)(e + 2) * 4];
        float4 w3 = *(const float4*)&wb[(size_t)(e + 3) * 4];
        const float4 *r0, *r1, *r2, *r3;
        if (mode == 0) {
            r0 = (const float4*)(g_H0 + (size_t)s0 * D1 + g * 128);
            r1 = (const float4*)(g_H0 + (size_t)s1 * D1 + g * 128);
            r2 = (const float4*)(g_H0 + (size_t)s2 * D1 + g * 128);
            r3 = (const float4*)(g_H0 + (size_t)s3 * D1 + g * 128);
        } else {
            r0 = (const float4*)(g_FA + (size_t)s0 * 128);
            r1 = (const float4*)(g_FA + (size_t)s1 * 128);
            r2 = (const float4*)(g_FA + (size_t)s2 * 128);
            r3 = (const float4*)(g_FA + (size_t)s3 * 128);
        }
        float4 v0 = r0[lane], v1 = r1[lane], v2 = r2[lane], v3 = r3[lane];
        float wv0 = sel4(w0, h), wv1 = sel4(w1, h), wv2 = sel4(w2, h), wv3 = sel4(w3, h);
        acc.x += wv0 * v0.x + wv1 * v1.x + wv2 * v2.x + wv3 * v3.x;
        acc.y += wv0 * v0.y + wv1 * v1.y + wv2 * v2.y + wv3 * v3.y;
        acc.z += wv0 * v0.z + wv1 * v1.z + wv2 * v2.z + wv3 * v3.z;
        acc.w += wv0 * v0.w + wv1 * v1.w + wv2 * v2.w + wv3 * v3.w;
    }
    for (; e < end; e++) {
        int s0 = g_SSRC[e];
        float4 w0 = *(const float4*)&wb[(size_t)e * 4];
        const float4* r0 = (mode == 0)
            ? (const float4*)(g_H0 + (size_t)s0 * D1 + g * 128)
            : (const float4*)(g_FA + (size_t)s0 * 128);
        float4 v0 = r0[lane];
        float wv0 = sel4(w0, h);
        acc.x += wv0 * v0.x; acc.y += wv0 * v0.y;
        acc.z += wv0 * v0.z; acc.w += wv0 * v0.w;
    }
    float4 inv4 = *(const float4*)&g_INV8[(size_t)d * 8 + g * 4];
    float invv = sel4(inv4, h);
    const float4* h0r = (const float4*)(g_H0 + (size_t)d * D1 + g * 128);
    float4 h0v = h0r[lane];
    float4 v;
    v.x = ONE_MB * acc.x * invv + BETA * h0v.x;
    v.y = ONE_MB * acc.y * invv + BETA * h0v.y;
    v.z = ONE_MB * acc.z * invv + BETA * h0v.z;
    v.w = ONE_MB * acc.w * invv + BETA * h0v.w;
    if (mode == 0) {
        ((float4*)(g_FA + (size_t)d * 128))[lane] = v;
    } else {
        v.x = (v.x > 0.f) ? v.x : expm1f(v.x);
        v.y = (v.y > 0.f) ? v.y : expm1f(v.y);
        v.z = (v.z > 0.f) ? v.z : expm1f(v.z);
        v.w = (v.w > 0.f) ? v.w : expm1f(v.w);
        ((float4*)(g_H0 + (size_t)d * D1 + g * 128))[lane] = v;
    }
}

// ------------------------------ output layer -----------------------------------
__global__ void st40_kernel(const float* __restrict__ a_src,
                            const float* __restrict__ a_dst) {
    int gw = blockIdx.x * 8 + (threadIdx.x >> 5);
    int lane = threadIdx.x & 31;
    if (gw >= NN) return;
    const float* row = g_O0 + (size_t)gw * NCLS;
    float s = row[lane] * a_src[lane];
    float t = row[lane] * a_dst[lane];
    if (lane < 8) {
        s += row[32 + lane] * a_src[32 + lane];
        t += row[32 + lane] * a_dst[32 + lane];
    }
    s = warp_sum(s);
    t = warp_sum(t);
    if (lane == 0) { g_S8[gw] = s; g_T8[gw] = t; }
}

__global__ void attn_w_kernel() {
    int d = blockIdx.x * 8 + (threadIdx.x >> 5);
    int lane = threadIdx.x & 31;
    if (d >= NN) return;
    int start = g_ROWPTR[d], end = g_ROWPTR[d + 1];
    if (start == end) return;
    float* wb = g_WBUF[0];
    float td = g_T8[d];
    float m = -INFINITY;
    for (int e = start + lane; e < end; e += 32) {
        float ev = g_S8[g_SSRC[e]] + td;
        ev = (ev >= 0.f) ? ev : LRA * ev;
        m = fmaxf(m, ev);
    }
    m = warp_max(m);
    float sum = 0.f;
    for (int e = start + lane; e < end; e += 32) {
        float ev = g_S8[g_SSRC[e]] + td;
        ev = (ev >= 0.f) ? ev : LRA * ev;
        float p = expf(ev - m);
        wb[e] = p;
        sum += p;
    }
    sum = warp_sum(sum);
    float inv = 1.f / (sum + 1e-16f);
    for (int e = start + lane; e < end; e += 32) wb[e] *= inv;
}

__global__ void hop40_kernel(int mode, float* __restrict__ out) {
    int d = blockIdx.x * 8 + (threadIdx.x >> 5);
    int lane = threadIdx.x & 31;
    if (d >= NN) return;
    int start = g_ROWPTR[d], end = g_ROWPTR[d + 1];
    float acca = 0.f, accb = 0.f;
    bool hi = (lane < 8);
    const float* base = (mode == 0) ? g_O0 : g_FA;
    const float* wb = g_WBUF[0];
    for (int e = start; e < end; e++) {
        int s = g_SSRC[e];
        float w = wb[e];
        const float* row = base + (size_t)s * NCLS;
        acca += w * row[lane];
        if (hi) accb += w * row[32 + lane];
    }
    const float* h0row = g_O0 + (size_t)d * NCLS;
    float va = ONE_MB * acca + BETA * h0row[lane];
    float vb = hi ? (ONE_MB * accb + BETA * h0row[32 + lane]) : 0.f;
    if (mode == 0) {
        float* orow = g_FA + (size_t)d * NCLS;
        orow[lane] = va;
        if (hi) orow[32 + lane] = vb;
    } else {
        float ea = (va > 0.f) ? va : expm1f(va);
        float eb = hi ? ((vb > 0.f) ? vb : expm1f(vb)) : -INFINITY;
        float mx = warp_max(fmaxf(ea, eb));
        float se = expf(ea - mx) + (hi ? expf(eb - mx) : 0.f);
        se = warp_sum(se);
        float lse = mx + logf(se);
        float* orow = out + (size_t)d * NCLS;
        orow[lane] = ea - lse;
        if (hi) orow[32 + lane] = eb - lse;
    }
}

// --------------------------------- launch -------------------------------------
extern "C" void kernel_launch(void* const* d_in, const int* in_sizes, int n_in,
                              void* d_out, int out_size) {
    const float* x     = (const float*)d_in[0];
    const void*  ei    = d_in[1];
    const float* W     = (const float*)d_in[2];
    const float* a_src = (const float*)d_in[3];
    const float* a_dst = (const float*)d_in[4];
    const float* Wout  = (const float*)d_in[5];
    const float* a_so  = (const float*)d_in[6];
    const float* a_do  = (const float*)d_in[7];
    float*       out   = (float*)d_out;

    // one-time side-stream setup (first call = uncaptured correctness run)
    static cudaStream_t s2 = nullptr;
    static cudaEvent_t evFork = nullptr, evCsr = nullptr;
    if (s2 == nullptr) {
        cudaStreamCreateWithFlags(&s2, cudaStreamNonBlocking);
        cudaEventCreateWithFlags(&evFork, cudaEventDisableTiming);
        cudaEventCreateWithFlags(&evCsr, cudaEventDisableTiming);
    }

    const int NWARP_GRID = (NN + 7) / 8;
    const int EGRID = (EE + 255) / 256;
    const int NGRID = (NN + 255) / 256;

    // fork: CSR build chain on s2, concurrent with gemm1+st8 on main stream
    cudaEventRecord(evFork, 0);
    cudaStreamWaitEvent(s2, evFork, 0);
    sniff_kernel<<<1, 256, 0, s2>>>((const int*)ei);
    zero_counts_kernel<<<NGRID, 256, 0, s2>>>();
    build_deg_kernel<<<EGRID, 256, 0, s2>>>(ei);
    scanA_kernel<<<NBLK, 256, 0, s2>>>();
    scanB_kernel<<<1, 128, 0, s2>>>();
    scanC_kernel<<<NBLK, 256, 0, s2>>>();
    scatter_kernel<<<EGRID, 256, 0, s2>>>(ei);
    cudaEventRecord(evCsr, s2);

    gemm1_kernel<<<dim3((NN + 127) / 128, D1 / 64), 256>>>(x, W);
    st8_kernel<<<NWARP_GRID, 256>>>(a_src, a_dst);

    // join: attention needs both CSR and st8
    cudaStreamWaitEvent(0, evCsr, 0);

    attn8_kernel<<<NWARP_GRID, 256>>>();
    for (int g = 0; g < 2; g++) {
        hop4_kernel<<<NWARP_GRID, 256>>>(g, 0);
        hop4_kernel<<<NWARP_GRID, 256>>>(g, 1);
    }

    gemm2_kernel<<<(NN + 255) / 256, 256>>>(Wout);

    st40_kernel<<<NWARP_GRID, 256>>>(a_so, a_do);
    attn_w_kernel<<<NWARP_GRID, 256>>>();
    hop40_kernel<<<NWARP_GRID, 256>>>(0, nullptr);
    hop40_kernel<<<NWARP_GRID, 256>>>(1, out);
}

// round 8
// speedup vs baseline: 1.0106x; 1.0106x over previous
#include <cuda_runtime.h>
#include <cuda_bf16.h>
#include <math.h>

#define NN 100000
#define EE 1600000
#define FIN 128
#define HID 32
#define HEADS 8
#define D1 256        // HEADS*HID
#define NCLS 40
#define BETA 0.1f
#define ONE_MB 0.9f   // 1-beta
#define LRA 0.2f      // leaky relu alpha
#define SCB 1024
#define NBLK ((NN + SCB - 1) / SCB)

// ------------- scratch (device globals; total ~248 MB, < 256 MB) -------------
__device__ __align__(128) float g_H0[(size_t)NN * D1];   // x@Wcat; layer-1 out in place
__device__ __align__(128) float g_FA[(size_t)NN * D1];   // hop-1 result (256-wide); GA aliases
__device__ __align__(128) float g_O0[(size_t)NN * NCLS]; // H @ W_out
__device__ __align__(128) float g_WL2[EE];               // layer-2 normalized weights
__device__ __align__(128) int   g_SSRC[EE];              // src sorted by dst (CSR)
__device__ __align__(128) float g_S8[(size_t)NN * 8];
__device__ __align__(128) float g_T8[(size_t)NN * 8];
__device__ __align__(128) float g_M8[(size_t)NN * 8];    // per-dst max (8 heads)
__device__ __align__(128) float g_INV8[(size_t)NN * 8];  // per-dst 1/denom (8 heads)
__device__ int   g_ROWPTR[NN + 1];
__device__ int   g_DEG[NN];
__device__ int   g_CUR[NN];
__device__ int   g_BSUM[NBLK];
__device__ int   g_BOFF[NBLK];
__device__ int   g_EI64;

// ------------------------------- helpers --------------------------------------
__device__ __forceinline__ float warp_sum(float v) {
#pragma unroll
    for (int o = 16; o > 0; o >>= 1) v += __shfl_xor_sync(0xffffffffu, v, o);
    return v;
}
__device__ __forceinline__ float warp_max(float v) {
#pragma unroll
    for (int o = 16; o > 0; o >>= 1) v = fmaxf(v, __shfl_xor_sync(0xffffffffu, v, o));
    return v;
}
__device__ __forceinline__ int warp_sum_i(int v) {
#pragma unroll
    for (int o = 16; o > 0; o >>= 1) v += __shfl_xor_sync(0xffffffffu, v, o);
    return v;
}

// ------------------------- edge dtype sniff (parallel) -------------------------
__global__ void sniff_kernel(const int* __restrict__ ei32) {
    int bad = 0;
    for (int i = threadIdx.x; i < 512; i += 256)
        bad |= (ei32[2 * i + 1] != 0);
    bad = __syncthreads_or(bad);
    if (threadIdx.x == 0) g_EI64 = bad ? 0 : 1;
}

__device__ __forceinline__ int load_node(const void* ei, size_t pos, int is64) {
    if (is64) return (int)((const long long*)ei)[pos];
    return ((const int*)ei)[pos];
}

// ------------------------------ CSR build -------------------------------------
__global__ void zero_counts_kernel() {
    int i = blockIdx.x * blockDim.x + threadIdx.x;
    if (i < NN) { g_DEG[i] = 0; g_CUR[i] = 0; }
}

__global__ void build_deg_kernel(const void* __restrict__ ei) {
    int e = blockIdx.x * blockDim.x + threadIdx.x;
    if (e >= EE) return;
    int d = load_node(ei, (size_t)EE + e, g_EI64);
    if ((unsigned)d < NN) atomicAdd(&g_DEG[d], 1);
}

__global__ void scanA_kernel() {
    __shared__ int wsum[8];
    int tid = threadIdx.x;
    int base = blockIdx.x * SCB + tid * 4;
    int s = 0;
#pragma unroll
    for (int j = 0; j < 4; j++) { int i = base + j; if (i < NN) s += g_DEG[i]; }
    s = warp_sum_i(s);
    if ((tid & 31) == 0) wsum[tid >> 5] = s;
    __syncthreads();
    if (tid == 0) {
        int t = 0;
#pragma unroll
        for (int w = 0; w < 8; w++) t += wsum[w];
        g_BSUM[blockIdx.x] = t;
    }
}

__global__ void scanB_kernel() {
    __shared__ int sm[4];
    int tid = threadIdx.x, lane = tid & 31, wid = tid >> 5;
    int v = (tid < NBLK) ? g_BSUM[tid] : 0;
    int x = v;
#pragma unroll
    for (int o = 1; o < 32; o <<= 1) {
        int y = __shfl_up_sync(0xffffffffu, x, o);
        if (lane >= o) x += y;
    }
    if (lane == 31) sm[wid] = x;
    __syncthreads();
    int woff = 0;
    for (int w = 0; w < wid; w++) woff += sm[w];
    if (tid < NBLK) g_BOFF[tid] = woff + x - v;
}

__global__ void scanC_kernel() {
    __shared__ int wsum[8];
    int tid = threadIdx.x, lane = tid & 31, wid = tid >> 5;
    int base = blockIdx.x * SCB + tid * 4;
    int a0 = (base + 0 < NN) ? g_DEG[base + 0] : 0;
    int a1 = (base + 1 < NN) ? g_DEG[base + 1] : 0;
    int a2 = (base + 2 < NN) ? g_DEG[base + 2] : 0;
    int a3 = (base + 3 < NN) ? g_DEG[base + 3] : 0;
    int tsum = a0 + a1 + a2 + a3;
    int x = tsum;
#pragma unroll
    for (int o = 1; o < 32; o <<= 1) {
        int y = __shfl_up_sync(0xffffffffu, x, o);
        if (lane >= o) x += y;
    }
    if (lane == 31) wsum[wid] = x;
    __syncthreads();
    int woff = 0;
    for (int w = 0; w < wid; w++) woff += wsum[w];
    int excl = g_BOFF[blockIdx.x] + woff + (x - tsum);
    if (base + 0 < NN) g_ROWPTR[base + 1] = excl + a0;
    if (base + 1 < NN) g_ROWPTR[base + 2] = excl + a0 + a1;
    if (base + 2 < NN) g_ROWPTR[base + 3] = excl + a0 + a1 + a2;
    if (base + 3 < NN) g_ROWPTR[base + 4] = excl + tsum;
    if (blockIdx.x == 0 && tid == 0) g_ROWPTR[0] = 0;
}

__global__ void scatter_kernel(const void* __restrict__ ei) {
    int e = blockIdx.x * blockDim.x + threadIdx.x;
    if (e >= EE) return;
    int is64 = g_EI64;
    int s = load_node(ei, (size_t)e, is64);
    int d = load_node(ei, (size_t)EE + e, is64);
    if ((unsigned)d >= NN || (unsigned)s >= NN) return;
    int pos = g_ROWPTR[d] + atomicAdd(&g_CUR[d], 1);
    if ((unsigned)pos < EE) g_SSRC[pos] = s;
}

// --------------------------------- GEMM1 --------------------------------------
__global__ void __launch_bounds__(256) gemm1_kernel(const float* __restrict__ x,
                                                    const float* __restrict__ W) {
    __shared__ float As[32][132];
    __shared__ float Bs[32][68];
    int tid = threadIdx.x;
    int tx = tid & 15;
    int ty = tid >> 4;
    int rowBase = blockIdx.x * 128;
    int colBase = blockIdx.y * 64;
    float acc[8][4] = {};
    for (int kt = 0; kt < FIN; kt += 32) {
#pragma unroll
        for (int p = 0; p < 4; p++) {
            int idx = tid + p * 256;
            int r = idx & 127;
            int kq = idx >> 7;
            int gr = rowBase + r;
            float4 v = make_float4(0.f, 0.f, 0.f, 0.f);
            if (gr < NN) v = *(const float4*)&x[(size_t)gr * FIN + kt + kq * 4];
            As[kq * 4 + 0][r] = v.x;
            As[kq * 4 + 1][r] = v.y;
            As[kq * 4 + 2][r] = v.z;
            As[kq * 4 + 3][r] = v.w;
        }
#pragma unroll
        for (int p = 0; p < 8; p++) {
            int idx = tid + p * 256;
            int nn = idx & 63;
            int k = idx >> 6;
            int col = colBase + nn;
            Bs[k][nn] = W[(size_t)(col >> 5) * (FIN * HID) + (size_t)(kt + k) * HID + (col & 31)];
        }
        __syncthreads();
#pragma unroll
        for (int k = 0; k < 32; k++) {
            float4 a0 = *(const float4*)&As[k][ty * 8];
            float4 a1 = *(const float4*)&As[k][ty * 8 + 4];
            float4 b  = *(const float4*)&Bs[k][tx * 4];
            float am[8] = {a0.x, a0.y, a0.z, a0.w, a1.x, a1.y, a1.z, a1.w};
            float bn[4] = {b.x, b.y, b.z, b.w};
#pragma unroll
            for (int i = 0; i < 8; i++)
#pragma unroll
                for (int j = 0; j < 4; j++)
                    acc[i][j] += am[i] * bn[j];
        }
        __syncthreads();
    }
#pragma unroll
    for (int i = 0; i < 8; i++) {
        int gr = rowBase + ty * 8 + i;
        if (gr < NN)
            *(float4*)&g_H0[(size_t)gr * D1 + colBase + tx * 4] =
                make_float4(acc[i][0], acc[i][1], acc[i][2], acc[i][3]);
    }
}

// --------------------------------- GEMM2 --------------------------------------
__global__ void gemm2_kernel(const float* __restrict__ Wout) {
    __shared__ float Bs[D1 * NCLS];
    int tid = threadIdx.x;
    for (int i = tid; i < D1 * NCLS; i += 256) Bs[i] = Wout[i];
    __syncthreads();
    int row = blockIdx.x * 256 + tid;
    if (row >= NN) return;
    const float* arow = g_H0 + (size_t)row * D1;
    float acc[NCLS] = {};
#pragma unroll 2
    for (int k4 = 0; k4 < D1; k4 += 4) {
        float4 a = *(const float4*)(arow + k4);
        float av[4] = {a.x, a.y, a.z, a.w};
#pragma unroll
        for (int kk = 0; kk < 4; kk++) {
            float av1 = av[kk];
            const float* b = &Bs[(k4 + kk) * NCLS];
#pragma unroll
            for (int c = 0; c < NCLS; c++) acc[c] += av1 * b[c];
        }
    }
    float* orow = g_O0 + (size_t)row * NCLS;
#pragma unroll
    for (int c = 0; c < NCLS; c++) orow[c] = acc[c];
}

// --------------------- attention s,t for ALL 8 heads at once ------------------
__global__ void st8_kernel(const float* __restrict__ a_src,
                           const float* __restrict__ a_dst) {
    int gw = blockIdx.x * 8 + (threadIdx.x >> 5);
    int lane = threadIdx.x & 31;
    if (gw >= NN) return;
    const float* row = g_H0 + (size_t)gw * D1;
#pragma unroll
    for (int h = 0; h < HEADS; h++) {
        float v = row[h * HID + lane];
        float s = warp_sum(v * a_src[h * HID + lane]);
        float t = warp_sum(v * a_dst[h * HID + lane]);
        if (lane == 0) { g_S8[(size_t)gw * 8 + h] = s; g_T8[(size_t)gw * 8 + h] = t; }
    }
}

// ---------- 8-head attention stats: per-dst max + inv-denominator only ----------
__global__ void attn8_kernel() {
    int d = blockIdx.x * 8 + (threadIdx.x >> 5);
    int lane = threadIdx.x & 31;
    if (d >= NN) return;
    int start = g_ROWPTR[d], end = g_ROWPTR[d + 1];
    if (start == end) {
        if (lane == 0) {
            float4 z = make_float4(0.f, 0.f, 0.f, 0.f);
            *(float4*)&g_INV8[(size_t)d * 8] = z;
            *(float4*)&g_INV8[(size_t)d * 8 + 4] = z;
            *(float4*)&g_M8[(size_t)d * 8] = z;
            *(float4*)&g_M8[(size_t)d * 8 + 4] = z;
        }
        return;
    }
    float4 ta = *(const float4*)&g_T8[(size_t)d * 8];
    float4 tb = *(const float4*)&g_T8[(size_t)d * 8 + 4];
    float t[8] = {ta.x, ta.y, ta.z, ta.w, tb.x, tb.y, tb.z, tb.w};
    float m[8];
#pragma unroll
    for (int i = 0; i < 8; i++) m[i] = -INFINITY;
    for (int e = start + lane; e < end; e += 32) {
        int s = g_SSRC[e];
        float4 sa = *(const float4*)&g_S8[(size_t)s * 8];
        float4 sb = *(const float4*)&g_S8[(size_t)s * 8 + 4];
        float sv[8] = {sa.x, sa.y, sa.z, sa.w, sb.x, sb.y, sb.z, sb.w};
#pragma unroll
        for (int i = 0; i < 8; i++) {
            float ev = sv[i] + t[i];
            ev = (ev >= 0.f) ? ev : LRA * ev;
            m[i] = fmaxf(m[i], ev);
        }
    }
#pragma unroll
    for (int i = 0; i < 8; i++) m[i] = warp_max(m[i]);
    float u[8] = {};
    for (int e = start + lane; e < end; e += 32) {
        int s = g_SSRC[e];
        float4 sa = *(const float4*)&g_S8[(size_t)s * 8];
        float4 sb = *(const float4*)&g_S8[(size_t)s * 8 + 4];
        float sv[8] = {sa.x, sa.y, sa.z, sa.w, sb.x, sb.y, sb.z, sb.w};
#pragma unroll
        for (int i = 0; i < 8; i++) {
            float ev = sv[i] + t[i];
            ev = (ev >= 0.f) ? ev : LRA * ev;
            u[i] += expf(ev - m[i]);
        }
    }
#pragma unroll
    for (int i = 0; i < 8; i++) u[i] = warp_sum(u[i]);
    if (lane == 0) {
        *(float4*)&g_M8[(size_t)d * 8]     = make_float4(m[0], m[1], m[2], m[3]);
        *(float4*)&g_M8[(size_t)d * 8 + 4] = make_float4(m[4], m[5], m[6], m[7]);
        *(float4*)&g_INV8[(size_t)d * 8] =
            make_float4(1.f / (u[0] + 1e-16f), 1.f / (u[1] + 1e-16f),
                        1.f / (u[2] + 1e-16f), 1.f / (u[3] + 1e-16f));
        *(float4*)&g_INV8[(size_t)d * 8 + 4] =
            make_float4(1.f / (u[4] + 1e-16f), 1.f / (u[5] + 1e-16f),
                        1.f / (u[6] + 1e-16f), 1.f / (u[7] + 1e-16f));
    }
}

// ---------- 8-head fused diffusion hop, weights recomputed on the fly ----------
// Warp per dst. lane handles cols [lane*4, lane*4+4) (head hA=lane>>3) and
// cols [128+lane*4, ...) (head hB=4+(lane>>3)).
// mode 0: gather H0 -> FA.  mode 1: gather FA -> elu -> H0 in place.
__global__ void hop8_kernel(int mode) {
    int d = blockIdx.x * 8 + (threadIdx.x >> 5);
    int lane = threadIdx.x & 31;
    if (d >= NN) return;
    int hA = lane >> 3;
    int hB = hA + 4;
    int start = g_ROWPTR[d], end = g_ROWPTR[d + 1];
    float tA = g_T8[(size_t)d * 8 + hA];
    float tB = g_T8[(size_t)d * 8 + hB];
    float mA = g_M8[(size_t)d * 8 + hA];
    float mB = g_M8[(size_t)d * 8 + hB];
    const float* src = mode ? g_FA : g_H0;
    float4 accA = make_float4(0.f, 0.f, 0.f, 0.f);
    float4 accB = make_float4(0.f, 0.f, 0.f, 0.f);
    int e = start;
    for (; e + 2 <= end; e += 2) {
        int s0 = g_SSRC[e], s1 = g_SSRC[e + 1];
        float sA0 = g_S8[(size_t)s0 * 8 + hA], sB0 = g_S8[(size_t)s0 * 8 + hB];
        float sA1 = g_S8[(size_t)s1 * 8 + hA], sB1 = g_S8[(size_t)s1 * 8 + hB];
        const float4* r0 = (const float4*)(src + (size_t)s0 * D1);
        const float4* r1 = (const float4*)(src + (size_t)s1 * D1);
        float4 vA0 = r0[lane], vB0 = r0[lane + 32];
        float4 vA1 = r1[lane], vB1 = r1[lane + 32];
        float eA0 = sA0 + tA; eA0 = (eA0 >= 0.f) ? eA0 : LRA * eA0;
        float eB0 = sB0 + tB; eB0 = (eB0 >= 0.f) ? eB0 : LRA * eB0;
        float eA1 = sA1 + tA; eA1 = (eA1 >= 0.f) ? eA1 : LRA * eA1;
        float eB1 = sB1 + tB; eB1 = (eB1 >= 0.f) ? eB1 : LRA * eB1;
        float pA0 = expf(eA0 - mA), pB0 = expf(eB0 - mB);
        float pA1 = expf(eA1 - mA), pB1 = expf(eB1 - mB);
        accA.x += pA0 * vA0.x + pA1 * vA1.x;
        accA.y += pA0 * vA0.y + pA1 * vA1.y;
        accA.z += pA0 * vA0.z + pA1 * vA1.z;
        accA.w += pA0 * vA0.w + pA1 * vA1.w;
        accB.x += pB0 * vB0.x + pB1 * vB1.x;
        accB.y += pB0 * vB0.y + pB1 * vB1.y;
        accB.z += pB0 * vB0.z + pB1 * vB1.z;
        accB.w += pB0 * vB0.w + pB1 * vB1.w;
    }
    if (e < end) {
        int s0 = g_SSRC[e];
        float sA0 = g_S8[(size_t)s0 * 8 + hA], sB0 = g_S8[(size_t)s0 * 8 + hB];
        const float4* r0 = (const float4*)(src + (size_t)s0 * D1);
        float4 vA0 = r0[lane], vB0 = r0[lane + 32];
        float eA0 = sA0 + tA; eA0 = (eA0 >= 0.f) ? eA0 : LRA * eA0;
        float eB0 = sB0 + tB; eB0 = (eB0 >= 0.f) ? eB0 : LRA * eB0;
        float pA0 = expf(eA0 - mA), pB0 = expf(eB0 - mB);
        accA.x += pA0 * vA0.x; accA.y += pA0 * vA0.y;
        accA.z += pA0 * vA0.z; accA.w += pA0 * vA0.w;
        accB.x += pB0 * vB0.x; accB.y += pB0 * vB0.y;
        accB.z += pB0 * vB0.z; accB.w += pB0 * vB0.w;
    }
    float invA = g_INV8[(size_t)d * 8 + hA];
    float invB = g_INV8[(size_t)d * 8 + hB];
    const float4* h0r = (const float4*)(g_H0 + (size_t)d * D1);
    float4 hA4 = h0r[lane], hB4 = h0r[lane + 32];
    float4 vA, vB;
    vA.x = ONE_MB * accA.x * invA + BETA * hA4.x;
    vA.y = ONE_MB * accA.y * invA + BETA * hA4.y;
    vA.z = ONE_MB * accA.z * invA + BETA * hA4.z;
    vA.w = ONE_MB * accA.w * invA + BETA * hA4.w;
    vB.x = ONE_MB * accB.x * invB + BETA * hB4.x;
    vB.y = ONE_MB * accB.y * invB + BETA * hB4.y;
    vB.z = ONE_MB * accB.z * invB + BETA * hB4.z;
    vB.w = ONE_MB * accB.w * invB + BETA * hB4.w;
    if (mode == 0) {
        float4* fr = (float4*)(g_FA + (size_t)d * D1);
        fr[lane] = vA;
        fr[lane + 32] = vB;
    } else {
        vA.x = (vA.x > 0.f) ? vA.x : expm1f(vA.x);
        vA.y = (vA.y > 0.f) ? vA.y : expm1f(vA.y);
        vA.z = (vA.z > 0.f) ? vA.z : expm1f(vA.z);
        vA.w = (vA.w > 0.f) ? vA.w : expm1f(vA.w);
        vB.x = (vB.x > 0.f) ? vB.x : expm1f(vB.x);
        vB.y = (vB.y > 0.f) ? vB.y : expm1f(vB.y);
        vB.z = (vB.z > 0.f) ? vB.z : expm1f(vB.z);
        vB.w = (vB.w > 0.f) ? vB.w : expm1f(vB.w);
        float4* hr = (float4*)(g_H0 + (size_t)d * D1);
        hr[lane] = vA;
        hr[lane + 32] = vB;
    }
}

// ------------------------------ output layer -----------------------------------
__global__ void st40_kernel(const float* __restrict__ a_src,
                            const float* __restrict__ a_dst) {
    int gw = blockIdx.x * 8 + (threadIdx.x >> 5);
    int lane = threadIdx.x & 31;
    if (gw >= NN) return;
    const float* row = g_O0 + (size_t)gw * NCLS;
    float s = row[lane] * a_src[lane];
    float t = row[lane] * a_dst[lane];
    if (lane < 8) {
        s += row[32 + lane] * a_src[32 + lane];
        t += row[32 + lane] * a_dst[32 + lane];
    }
    s = warp_sum(s);
    t = warp_sum(t);
    if (lane == 0) { g_S8[gw] = s; g_T8[gw] = t; }   // stride-1 reuse
}

__global__ void attn_w_kernel() {
    int d = blockIdx.x * 8 + (threadIdx.x >> 5);
    int lane = threadIdx.x & 31;
    if (d >= NN) return;
    int start = g_ROWPTR[d], end = g_ROWPTR[d + 1];
    if (start == end) return;
    float td = g_T8[d];
    float m = -INFINITY;
    for (int e = start + lane; e < end; e += 32) {
        float ev = g_S8[g_SSRC[e]] + td;
        ev = (ev >= 0.f) ? ev : LRA * ev;
        m = fmaxf(m, ev);
    }
    m = warp_max(m);
    float sum = 0.f;
    for (int e = start + lane; e < end; e += 32) {
        float ev = g_S8[g_SSRC[e]] + td;
        ev = (ev >= 0.f) ? ev : LRA * ev;
        float p = expf(ev - m);
        g_WL2[e] = p;
        sum += p;
    }
    sum = warp_sum(sum);
    float inv = 1.f / (sum + 1e-16f);
    for (int e = start + lane; e < end; e += 32) g_WL2[e] *= inv;
}

__global__ void hop40_kernel(int mode, float* __restrict__ out) {
    int d = blockIdx.x * 8 + (threadIdx.x >> 5);
    int lane = threadIdx.x & 31;
    if (d >= NN) return;
    int start = g_ROWPTR[d], end = g_ROWPTR[d + 1];
    float acca = 0.f, accb = 0.f;
    bool hi = (lane < 8);
    const float* base = (mode == 0) ? g_O0 : g_FA;   // g_FA doubles as GA
    for (int e = start; e < end; e++) {
        int s = g_SSRC[e];
        float w = g_WL2[e];
        const float* row = base + (size_t)s * NCLS;
        acca += w * row[lane];
        if (hi) accb += w * row[32 + lane];
    }
    const float* h0row = g_O0 + (size_t)d * NCLS;
    float va = ONE_MB * acca + BETA * h0row[lane];
    float vb = hi ? (ONE_MB * accb + BETA * h0row[32 + lane]) : 0.f;
    if (mode == 0) {
        float* orow = g_FA + (size_t)d * NCLS;
        orow[lane] = va;
        if (hi) orow[32 + lane] = vb;
    } else {
        float ea = (va > 0.f) ? va : expm1f(va);
        float eb = hi ? ((vb > 0.f) ? vb : expm1f(vb)) : -INFINITY;
        float mx = warp_max(fmaxf(ea, eb));
        float se = expf(ea - mx) + (hi ? expf(eb - mx) : 0.f);
        se = warp_sum(se);
        float lse = mx + logf(se);
        float* orow = out + (size_t)d * NCLS;
        orow[lane] = ea - lse;
        if (hi) orow[32 + lane] = eb - lse;
    }
}

// --------------------------------- launch -------------------------------------
extern "C" void kernel_launch(void* const* d_in, const int* in_sizes, int n_in,
                              void* d_out, int out_size) {
    const float* x     = (const float*)d_in[0];
    const void*  ei    = d_in[1];
    const float* W     = (const float*)d_in[2];
    const float* a_src = (const float*)d_in[3];
    const float* a_dst = (const float*)d_in[4];
    const float* Wout  = (const float*)d_in[5];
    const float* a_so  = (const float*)d_in[6];
    const float* a_do  = (const float*)d_in[7];
    float*       out   = (float*)d_out;

    const int NWARP_GRID = (NN + 7) / 8;
    const int EGRID = (EE + 255) / 256;
    const int NGRID = (NN + 255) / 256;

    sniff_kernel<<<1, 256>>>((const int*)ei);
    zero_counts_kernel<<<NGRID, 256>>>();
    build_deg_kernel<<<EGRID, 256>>>(ei);
    scanA_kernel<<<NBLK, 256>>>();
    scanB_kernel<<<1, 128>>>();
    scanC_kernel<<<NBLK, 256>>>();
    scatter_kernel<<<EGRID, 256>>>(ei);

    gemm1_kernel<<<dim3((NN + 127) / 128, D1 / 64), 256>>>(x, W);
    st8_kernel<<<NWARP_GRID, 256>>>(a_src, a_dst);
    attn8_kernel<<<NWARP_GRID, 256>>>();

    hop8_kernel<<<NWARP_GRID, 256>>>(0);
    hop8_kernel<<<NWARP_GRID, 256>>>(1);

    gemm2_kernel<<<(NN + 255) / 256, 256>>>(Wout);

    st40_kernel<<<NWARP_GRID, 256>>>(a_so, a_do);
    attn_w_kernel<<<NWARP_GRID, 256>>>();
    hop40_kernel<<<NWARP_GRID, 256>>>(0, nullptr);
    hop40_kernel<<<NWARP_GRID, 256>>>(1, out);
}